// round 13
// baseline (speedup 1.0000x reference)
#include <cuda_runtime.h>

#define NMAX 100000
#define M1MAX 200000
#define M2MAX 100000

// ---------------- scratch (device globals; no allocations) ----------------
__device__ float g_cref[4][NMAX];           // per-branch c_ref = refp . att[:64]
__device__ float g_l1[4][NMAX];             // per-branch L1(refp)
__device__ float g_E[4][(size_t)NMAX * 64]; // e_attr0, e_rel0, e_attr1, e_rel1
__device__ float g_E0[(size_t)NMAX * 64];   // elu-combined relation-0 embedding
__device__ float g_E1[(size_t)NMAX * 64];   // elu-combined relation-1 embedding
__device__ float g_acc[7 * 64];             // tanh-GEMV column sums
__device__ float g_beta[8];                 // 0-3 intra betas, 4-6 inter betas
__device__ float2 g_cd_t1[M1MAX];           // h1:  (row.att2, L1)
__device__ float2 g_cd_r1[M1MAX];           // rf1
__device__ float2 g_cd_t2[M2MAX];           // h2
__device__ float2 g_cd_r2[M2MAX];           // rf2

// ---------------- helpers ----------------
static __device__ __forceinline__ float2 ffma2(float2 a, float2 b, float2 c) {
    float2 d;
    asm("fma.rn.f32x2 %0, %1, %2, %3;"
        : "=l"(reinterpret_cast<unsigned long long &>(d))
        : "l"(reinterpret_cast<unsigned long long &>(a)),
          "l"(reinterpret_cast<unsigned long long &>(b)),
          "l"(reinterpret_cast<unsigned long long &>(c)));
    return d;
}

static __device__ __forceinline__ float2 wred2(float2 v) {
#pragma unroll
    for (int m = 16; m > 0; m >>= 1) {
        v.x += __shfl_xor_sync(0xffffffffu, v.x, m);
        v.y += __shfl_xor_sync(0xffffffffu, v.y, m);
    }
    return v;
}

static __device__ __forceinline__ float wredf(float v) {
#pragma unroll
    for (int m = 16; m > 0; m >>= 1) v += __shfl_xor_sync(0xffffffffu, v, m);
    return v;
}

static __device__ __forceinline__ float eluf(float x) { return x > 0.f ? x : expm1f(x); }

static __device__ __forceinline__ float tanha(float x) {
    float y;
    asm("tanh.approx.f32 %0, %1;" : "=f"(y) : "f"(x));
    return y;
}

extern __shared__ float smdyn[];

// GEMM-tile constants: M=128 nodes, N=64 outputs, K=64. 128 thr = 16(m) x 8(n).
// Thread (im,in) owns m = 8*im..8*im+7 and j in {4*in..4*in+3, 32+4*in..32+4*in+3}.
#define XS_F 8192   // xs[64][128]  transposed x
#define WS_F 4096   // ws[64][64]   transposed W (ws[k][j] = W[j][k])

// stage W transposed into ws: thread t: j=t&63, k-half=t>>6
static __device__ __forceinline__ void stage_w(float *ws, const float *__restrict__ W,
                                               int tid) {
    int j = tid & 63, half = tid >> 6;
    const float4 *wg = (const float4 *)(W + j * 64 + half * 32);
#pragma unroll
    for (int i = 0; i < 8; i++) {
        float4 w4 = __ldg(wg + i);
        int k = half * 32 + 4 * i;
        ws[k * 64 + j] = w4.x;
        ws[(k + 1) * 64 + j] = w4.y;
        ws[(k + 2) * 64 + j] = w4.z;
        ws[(k + 3) * 64 + j] = w4.w;
    }
}

// stage one x row (row rr of x) into transposed xs column tid
static __device__ __forceinline__ void stage_x(float *xs, const float *__restrict__ x,
                                               int rr, int tid) {
    const float4 *xg = (const float4 *)(x + (size_t)rr * 64);
#pragma unroll
    for (int i = 0; i < 16; i++) {
        float4 v = __ldg(xg + i);
        int k = 4 * i;
        xs[k * 128 + tid] = v.x;
        xs[(k + 1) * 128 + tid] = v.y;
        xs[(k + 2) * 128 + tid] = v.z;
        xs[(k + 3) * 128 + tid] = v.w;
    }
}

// software-pipelined 8x8 register-tile K-loop, conflict-free W loads.
#define FMA_M(CX)                                                        \
    do {                                                                 \
        float2 xd = make_float2(CX, CX);                                 \
        acc[MM][0] = ffma2(xd, q0, acc[MM][0]);                          \
        acc[MM][1] = ffma2(xd, q1, acc[MM][1]);                          \
        acc[MM][2] = ffma2(xd, q2, acc[MM][2]);                          \
        acc[MM][3] = ffma2(xd, q3, acc[MM][3]);                          \
    } while (0)

static __device__ __forceinline__ void mm_loop(const float *xs, const float *ws,
                                               float2 acc[8][4], int im, int in) {
    const float4 *xp = (const float4 *)&xs[8 * im];        // +32 float4 per k
    const float4 *wap = (const float4 *)&ws[4 * in];       // j block 0: +16/k
    const float4 *wbp = (const float4 *)&ws[32 + 4 * in];  // j block 1
    float4 x0 = xp[0], x1 = xp[1];
    float4 wa = wap[0], wb = wbp[0];
#pragma unroll 2
    for (int k = 0; k < 64; k++) {
        float4 cx0 = x0, cx1 = x1, cwa = wa, cwb = wb;
        if (k < 63) {
            xp += 32; wap += 16; wbp += 16;
            x0 = xp[0]; x1 = xp[1];
            wa = wap[0]; wb = wbp[0];
        }
        float2 q0 = make_float2(cwa.x, cwa.y), q1 = make_float2(cwa.z, cwa.w);
        float2 q2 = make_float2(cwb.x, cwb.y), q3 = make_float2(cwb.z, cwb.w);
        {
#define MM 0
            FMA_M(cx0.x);
#undef MM
#define MM 1
            FMA_M(cx0.y);
#undef MM
#define MM 2
            FMA_M(cx0.z);
#undef MM
#define MM 3
            FMA_M(cx0.w);
#undef MM
#define MM 4
            FMA_M(cx1.x);
#undef MM
#define MM 5
            FMA_M(cx1.y);
#undef MM
#define MM 6
            FMA_M(cx1.z);
#undef MM
#define MM 7
            FMA_M(cx1.w);
#undef MM
        }
    }
}

// ---------------- kernels ----------------
__global__ void init_kernel() {
    int t = threadIdx.x;
    if (t < 7 * 64) g_acc[t] = 0.f;
}

// Per-table-row precompute: out[row] = (row . att2, L1(row)) for two tables.
__global__ void __launch_bounds__(256) precomp_kernel(
    const float *__restrict__ tab, const float *__restrict__ rtab,
    float2 *__restrict__ outT, float2 *__restrict__ outR,
    const float *__restrict__ attT2, const float *__restrict__ attR2, int m) {
    int w = threadIdx.x >> 5, l = threadIdx.x & 31;
    float2 aT = __ldg((const float2 *)attT2 + l);
    float2 aR = __ldg((const float2 *)attR2 + l);
    int row = blockIdx.x * 8 + w;
    if (row >= m) return;
    float2 v = __ldg((const float2 *)(tab + (size_t)row * 64) + l);
    float2 q = wred2(make_float2(v.x * aT.x + v.y * aT.y, fabsf(v.x) + fabsf(v.y)));
    float2 u = __ldg((const float2 *)(rtab + (size_t)row * 64) + l);
    float2 p = wred2(make_float2(u.x * aR.x + u.y * aR.y, fabsf(u.x) + fabsf(u.y)));
    if (l == 0) { outT[row] = q; outR[row] = p; }
}

// Block-GEMM prep + tf-gemv:
// y=0:(h0,Wr0,att0)->s0  y=1:(h0,Wr1,att1)->s2
// y=2:(rf0,Wr2_0,att2_0)->s1  y=3:(rf0,Wr2_1,att2_1)->s3
// y=4: tanh column sums of tf @ interW^T + interb -> g_acc slot 6
// dyn smem floats: xs 8192 | ws 4096 | par 128 | red 1024
__global__ void __launch_bounds__(128, 4) prep_g(
    const float *__restrict__ h0, const float *__restrict__ rf0,
    const float *__restrict__ tf,
    const float *__restrict__ W0, const float *__restrict__ b0, const float *__restrict__ a0,
    const float *__restrict__ W1, const float *__restrict__ b1, const float *__restrict__ a1,
    const float *__restrict__ W2, const float *__restrict__ b2, const float *__restrict__ a2,
    const float *__restrict__ W3, const float *__restrict__ b3, const float *__restrict__ a3,
    const float *__restrict__ interW, const float *__restrict__ interb,
    int n) {
    float *xs = smdyn, *ws = smdyn + XS_F, *par = ws + WS_F, *red = par + 128;
    int y = blockIdx.y;
    const float *x, *W, *b, *att;
    int slot;
    if (y == 0)      { x = h0;  W = W0; b = b0; att = a0; slot = 0; }
    else if (y == 1) { x = h0;  W = W1; b = b1; att = a1; slot = 2; }
    else if (y == 2) { x = rf0; W = W2; b = b2; att = a2; slot = 1; }
    else if (y == 3) { x = rf0; W = W3; b = b3; att = a3; slot = 3; }
    else             { x = tf;  W = interW; b = interb; att = interb; slot = 6; }
    int tid = threadIdx.x;
    stage_w(ws, W, tid);
    if (tid < 64) { par[tid] = b[tid]; par[64 + tid] = att[tid]; }
    int base = blockIdx.x * 128;
    int r = base + tid;
    bool act = (r < n);
    stage_x(xs, x, act ? r : (n - 1), tid);
    __syncthreads();
    int im = tid >> 3, in = tid & 7;
    float2 acc[8][4];
#pragma unroll
    for (int m = 0; m < 8; m++)
#pragma unroll
        for (int p = 0; p < 4; p++) acc[m][p] = make_float2(0.f, 0.f);
    mm_loop(xs, ws, acc, im, in);
    int jb[4] = {4 * in, 4 * in + 2, 32 + 4 * in, 32 + 4 * in + 2};
    if (y < 4) {
        float crv[8], l1v[8];
#pragma unroll
        for (int m = 0; m < 8; m++) {
            float cr = 0.f, l1 = 0.f;
#pragma unroll
            for (int p = 0; p < 4; p++) {
                int j = jb[p];
                float r0 = acc[m][p].x + par[j];
                float r1 = acc[m][p].y + par[j + 1];
                cr = fmaf(r0, par[64 + j], cr);
                cr = fmaf(r1, par[64 + j + 1], cr);
                l1 += fabsf(r0) + fabsf(r1);
            }
            crv[m] = cr; l1v[m] = l1;
        }
        __syncthreads();
#pragma unroll
        for (int m = 0; m < 8; m++) red[in * 128 + 8 * im + m] = crv[m];
        __syncthreads();
        float crt = 0.f;
#pragma unroll
        for (int q = 0; q < 8; q++) crt += red[q * 128 + tid];
        __syncthreads();
#pragma unroll
        for (int m = 0; m < 8; m++) red[in * 128 + 8 * im + m] = l1v[m];
        __syncthreads();
        float l1t = 0.f;
#pragma unroll
        for (int q = 0; q < 8; q++) l1t += red[q * 128 + tid];
        if (act) { g_cref[slot][r] = crt; g_l1[slot][r] = l1t; }
    } else {
        float s[8];
#pragma unroll
        for (int jj = 0; jj < 8; jj++) s[jj] = 0.f;
#pragma unroll
        for (int m = 0; m < 8; m++) {
            bool am = (base + 8 * im + m) < n;
#pragma unroll
            for (int p = 0; p < 4; p++) {
                int j = jb[p];
                if (am) {
                    s[2 * p] += tanha(acc[m][p].x + par[j]);
                    s[2 * p + 1] += tanha(acc[m][p].y + par[j + 1]);
                }
            }
        }
        __syncthreads();
#pragma unroll
        for (int p = 0; p < 4; p++) {
            red[im * 64 + jb[p]] = s[2 * p];
            red[im * 64 + jb[p] + 1] = s[2 * p + 1];
        }
        __syncthreads();
        if (tid < 64) {
            float tot = 0.f;
#pragma unroll
            for (int q = 0; q < 16; q++) tot += red[q * 64 + tid];
            atomicAdd(&g_acc[slot * 64 + tid], tot);
        }
    }
}

// Block-GEMM tanh column sums for the 4 E branches (y=0..3).
__global__ void __launch_bounds__(128, 4) gemv_g(
    const float *__restrict__ aggW0, const float *__restrict__ aggb0,
    const float *__restrict__ aggW1, const float *__restrict__ aggb1, int n) {
    float *xs = smdyn, *ws = smdyn + XS_F, *bs = ws + WS_F, *red = bs + 64;
    int y = blockIdx.y;
    const float *x = g_E[y];
    const float *W = (y < 2) ? aggW0 : aggW1;
    const float *b = (y < 2) ? aggb0 : aggb1;
    int slot = y;
    int tid = threadIdx.x;
    stage_w(ws, W, tid);
    if (tid < 64) bs[tid] = b[tid];
    int base = blockIdx.x * 128;
    int r = base + tid;
    stage_x(xs, x, (r < n) ? r : (n - 1), tid);
    __syncthreads();
    int im = tid >> 3, in = tid & 7;
    float2 acc[8][4];
#pragma unroll
    for (int m = 0; m < 8; m++)
#pragma unroll
        for (int p = 0; p < 4; p++) acc[m][p] = make_float2(0.f, 0.f);
    mm_loop(xs, ws, acc, im, in);
    int jb[4] = {4 * in, 4 * in + 2, 32 + 4 * in, 32 + 4 * in + 2};
    float s[8];
#pragma unroll
    for (int jj = 0; jj < 8; jj++) s[jj] = 0.f;
#pragma unroll
    for (int m = 0; m < 8; m++) {
        bool am = (base + 8 * im + m) < n;
#pragma unroll
        for (int p = 0; p < 4; p++) {
            int j = jb[p];
            if (am) {
                s[2 * p] += tanha(acc[m][p].x + bs[j]);
                s[2 * p + 1] += tanha(acc[m][p].y + bs[j + 1]);
            }
        }
    }
    __syncthreads();
#pragma unroll
    for (int p = 0; p < 4; p++) {
        red[im * 64 + jb[p]] = s[2 * p];
        red[im * 64 + jb[p] + 1] = s[2 * p + 1];
    }
    __syncthreads();
    if (tid < 64) {
        float tot = 0.f;
#pragma unroll
        for (int q = 0; q < 16; q++) tot += red[q * 64 + tid];
        atomicAdd(&g_acc[slot * 64 + tid], tot);
    }
}

// fused: c = elu(ba*eA + bb*eB); store c; tanh column sums of c@interW^T+b.
__global__ void __launch_bounds__(128, 4) combine_g(
    const float *__restrict__ interW, const float *__restrict__ interb, int n) {
    float *xs = smdyn, *ws = smdyn + XS_F, *bs = ws + WS_F, *red = bs + 64;
    int y = blockIdx.y;
    const float *eA = g_E[2 * y], *eB = g_E[2 * y + 1];
    float *outb = y ? g_E1 : g_E0;
    float ba = g_beta[2 * y], bb = g_beta[2 * y + 1];
    int tid = threadIdx.x;
    stage_w(ws, interW, tid);
    if (tid < 64) bs[tid] = interb[tid];
    int base = blockIdx.x * 128;
    int r = base + tid;
    bool act = (r < n);
    int rr = act ? r : (n - 1);
    {
        const float4 *ag = (const float4 *)(eA + (size_t)rr * 64);
        const float4 *bg = (const float4 *)(eB + (size_t)rr * 64);
        float4 *og = (float4 *)(outb + (size_t)rr * 64);
#pragma unroll
        for (int i = 0; i < 16; i++) {
            float4 a = __ldg(ag + i), v = __ldg(bg + i);
            float4 c;
            c.x = eluf(ba * a.x + bb * v.x);
            c.y = eluf(ba * a.y + bb * v.y);
            c.z = eluf(ba * a.z + bb * v.z);
            c.w = eluf(ba * a.w + bb * v.w);
            if (act) og[i] = c;
            int k = 4 * i;
            xs[k * 128 + tid] = c.x;
            xs[(k + 1) * 128 + tid] = c.y;
            xs[(k + 2) * 128 + tid] = c.z;
            xs[(k + 3) * 128 + tid] = c.w;
        }
    }
    __syncthreads();
    int im = tid >> 3, in = tid & 7;
    float2 acc[8][4];
#pragma unroll
    for (int m = 0; m < 8; m++)
#pragma unroll
        for (int p = 0; p < 4; p++) acc[m][p] = make_float2(0.f, 0.f);
    mm_loop(xs, ws, acc, im, in);
    int jb[4] = {4 * in, 4 * in + 2, 32 + 4 * in, 32 + 4 * in + 2};
    float s[8];
#pragma unroll
    for (int jj = 0; jj < 8; jj++) s[jj] = 0.f;
#pragma unroll
    for (int m = 0; m < 8; m++) {
        bool am = (base + 8 * im + m) < n;
#pragma unroll
        for (int p = 0; p < 4; p++) {
            int j = jb[p];
            if (am) {
                s[2 * p] += tanha(acc[m][p].x + bs[j]);
                s[2 * p + 1] += tanha(acc[m][p].y + bs[j + 1]);
            }
        }
    }
    __syncthreads();
#pragma unroll
    for (int p = 0; p < 4; p++) {
        red[im * 64 + jb[p]] = s[2 * p];
        red[im * 64 + jb[p] + 1] = s[2 * p + 1];
    }
    __syncthreads();
    if (tid < 64) {
        float tot = 0.f;
#pragma unroll
        for (int q = 0; q < 16; q++) tot += red[q * 64 + tid];
        atomicAdd(&g_acc[(4 + y) * 64 + tid], tot);
    }
}

static __device__ __forceinline__ void do_branch_v2(
    const float *__restrict__ tab, const float2 *__restrict__ cdl1,
    const int *idx, float cref, float l1ref, float *__restrict__ eout, int l) {
    float2 v[8];
    float sc[8];
#pragma unroll
    for (int s = 0; s < 8; s++)
        v[s] = __ldg((const float2 *)(tab + (size_t)idx[s] * 64) + l);
#pragma unroll
    for (int s = 0; s < 8; s++) {
        float2 cd = __ldg(cdl1 + idx[s]);
        float t = __fdividef(cref + cd.x, fmaxf(l1ref + cd.y, 1e-12f));
        sc[s] = t > 0.f ? t : 0.01f * t;  // leaky_relu 0.01
    }
    float mx = sc[0];
#pragma unroll
    for (int s = 1; s < 8; s++) mx = fmaxf(mx, sc[s]);
    float sum = 0.f;
#pragma unroll
    for (int s = 0; s < 8; s++) { sc[s] = __expf(sc[s] - mx); sum += sc[s]; }
    float inv = __fdividef(1.f, sum);
    float2 o = make_float2(0.f, 0.f);
#pragma unroll
    for (int s = 0; s < 8; s++) {
        float ww = sc[s] * inv;
        o.x = fmaf(ww, v[s].x, o.x);
        o.y = fmaf(ww, v[s].y, o.y);
    }
    *((float2 *)eout + l) = o;
}

// warp-per-(node, branch) attention: 8 warps = 4 nodes x 2 branches per block.
__global__ void __launch_bounds__(256) attn_y(
    const float *__restrict__ t1, const float *__restrict__ r1, const int *__restrict__ n0,
    const float *__restrict__ t2, const float *__restrict__ r2, const int *__restrict__ n1,
    int n) {
    int y = blockIdx.y;
    const float *tab = y ? t2 : t1;
    const float *rtab = y ? r2 : r1;
    const int *nei = y ? n1 : n0;
    const float2 *cdA = y ? g_cd_t2 : g_cd_t1;
    const float2 *cdR = y ? g_cd_r2 : g_cd_r1;
    int cidx = y * 2;
    int tid = threadIdx.x, w = tid >> 5, l = tid & 31;
    int node = blockIdx.x * 4 + (w >> 1);
    int br = w & 1;
    if (node >= n) return;
    const float *t = br ? rtab : tab;
    const float2 *cd = br ? cdR : cdA;
    int slot = cidx + br;
    const int4 *np = (const int4 *)(nei + (size_t)node * 8);
    int4 i0 = __ldg(np), i1 = __ldg(np + 1);
    int idx[8] = {i0.x, i0.y, i0.z, i0.w, i1.x, i1.y, i1.z, i1.w};
    do_branch_v2(t, cd, idx, g_cref[slot][node], g_l1[slot][node],
                 &g_E[slot][(size_t)node * 64], l);
}

__global__ void beta_rel_kernel(const float *__restrict__ agg0,
                                const float *__restrict__ agg1, int n) {
    int tid = threadIdx.x;
    int r = tid >> 5, l = tid & 31;
    if (r > 1) return;
    const float *aat = r ? agg1 : agg0;
    float invN = 1.f / (float)n;
    float2 at = __ldg((const float2 *)aat + l);
    const float *accA = g_acc + (2 * r) * 64;
    const float *accB = g_acc + (2 * r + 1) * 64;
    float pa = (accA[2 * l] * invN) * at.x + (accA[2 * l + 1] * invN) * at.y;
    float pb = (accB[2 * l] * invN) * at.x + (accB[2 * l + 1] * invN) * at.y;
    float2 q = wred2(make_float2(pa, pb));
    if (l == 0) {
        float m = fmaxf(q.x, q.y);
        float ea = expf(q.x - m), eb = expf(q.y - m);
        float inv = 1.f / (ea + eb);
        g_beta[2 * r] = ea * inv;
        g_beta[2 * r + 1] = eb * inv;
    }
}

__global__ void beta_inter_kernel(const float *__restrict__ interatt, int n) {
    int l = threadIdx.x;
    float invN = 1.f / (float)n;
    float2 at = __ldg((const float2 *)interatt + l);
    float p[3];
#pragma unroll
    for (int k = 0; k < 3; k++) {
        float px = (g_acc[(4 + k) * 64 + 2 * l] * invN) * at.x +
                   (g_acc[(4 + k) * 64 + 2 * l + 1] * invN) * at.y;
        p[k] = wredf(px);
    }
    if (l == 0) {
        float m = fmaxf(p[0], fmaxf(p[1], p[2]));
        float e0 = expf(p[0] - m), e1 = expf(p[1] - m), e2 = expf(p[2] - m);
        float inv = 1.f / (e0 + e1 + e2);
        g_beta[4] = e0 * inv;
        g_beta[5] = e1 * inv;
        g_beta[6] = e2 * inv;
    }
}

__global__ void final_kernel(const float *__restrict__ tf, float *__restrict__ out, int n) {
    int i = blockIdx.x * blockDim.x + threadIdx.x;
    if (i >= n * 32) return;
    float b0 = g_beta[4], b1 = g_beta[5], b2 = g_beta[6];
    float2 e0 = ((const float2 *)g_E0)[i];
    float2 e1 = ((const float2 *)g_E1)[i];
    float2 t = ((const float2 *)tf)[i];
    float2 o;
    o.x = b0 * e0.x + b1 * e1.x + b2 * t.x;
    o.y = b0 * e0.y + b1 * e1.y + b2 * t.y;
    ((float2 *)out)[i] = o;
}

// ---------------- launch ----------------
extern "C" void kernel_launch(void *const *d_in, const int *in_sizes, int n_in,
                              void *d_out, int out_size) {
    const float *tf = (const float *)d_in[0];
    const float *h0 = (const float *)d_in[1];
    const float *h1 = (const float *)d_in[2];
    const float *h2 = (const float *)d_in[3];
    const float *rf0 = (const float *)d_in[4];
    const float *rf1 = (const float *)d_in[5];
    const float *rf2 = (const float *)d_in[6];
    const int *nei0 = (const int *)d_in[7];
    const int *nei1 = (const int *)d_in[8];
    const float *att0 = (const float *)d_in[9];
    const float *att2_0 = (const float *)d_in[10];
    const float *Wr0 = (const float *)d_in[11];
    const float *br0 = (const float *)d_in[12];
    const float *Wr2_0 = (const float *)d_in[13];
    const float *br2_0 = (const float *)d_in[14];
    const float *aggW0 = (const float *)d_in[15];
    const float *aggb0 = (const float *)d_in[16];
    const float *aggatt0 = (const float *)d_in[17];
    const float *att1 = (const float *)d_in[18];
    const float *att2_1 = (const float *)d_in[19];
    const float *Wr1 = (const float *)d_in[20];
    const float *br1 = (const float *)d_in[21];
    const float *Wr2_1 = (const float *)d_in[22];
    const float *br2_1 = (const float *)d_in[23];
    const float *aggW1 = (const float *)d_in[24];
    const float *aggb1 = (const float *)d_in[25];
    const float *aggatt1 = (const float *)d_in[26];
    const float *interW = (const float *)d_in[27];
    const float *interb = (const float *)d_in[28];
    const float *interatt = (const float *)d_in[29];

    int n = in_sizes[0] / 64;
    if (n > NMAX) n = NMAX;
    int m1 = in_sizes[2] / 64; if (m1 > M1MAX) m1 = M1MAX;
    int m2 = in_sizes[3] / 64; if (m2 > M2MAX) m2 = M2MAX;
    float *out = (float *)d_out;

    float2 *cd_t1, *cd_r1, *cd_t2, *cd_r2;
    cudaGetSymbolAddress((void **)&cd_t1, g_cd_t1);
    cudaGetSymbolAddress((void **)&cd_r1, g_cd_r1);
    cudaGetSymbolAddress((void **)&cd_t2, g_cd_t2);
    cudaGetSymbolAddress((void **)&cd_r2, g_cd_r2);

    const int PREP_SMEM = (XS_F + WS_F + 128 + 1024) * 4;   // 53760 B
    const int GEMV_SMEM = (XS_F + WS_F + 64 + 1024) * 4;    // 53504 B
    cudaFuncSetAttribute(prep_g, cudaFuncAttributeMaxDynamicSharedMemorySize, PREP_SMEM);
    cudaFuncSetAttribute(gemv_g, cudaFuncAttributeMaxDynamicSharedMemorySize, GEMV_SMEM);
    cudaFuncSetAttribute(combine_g, cudaFuncAttributeMaxDynamicSharedMemorySize, GEMV_SMEM);

    init_kernel<<<1, 512>>>();

    precomp_kernel<<<(m1 + 7) / 8, 256>>>(h1, rf1, cd_t1, cd_r1, att0 + 64, att2_0 + 64, m1);
    precomp_kernel<<<(m2 + 7) / 8, 256>>>(h2, rf2, cd_t2, cd_r2, att1 + 64, att2_1 + 64, m2);

    int tiles = (n + 127) / 128;

    // prep (4 branch slices) + tf inter tanh sums (slice 4), one launch
    prep_g<<<dim3(tiles, 5), 128, PREP_SMEM>>>(h0, rf0, tf,
                                               Wr0, br0, att0,
                                               Wr1, br1, att1,
                                               Wr2_0, br2_0, att2_0,
                                               Wr2_1, br2_1, att2_1,
                                               interW, interb, n);

    // warp-per-(node,branch) attention, both relations
    attn_y<<<dim3((n + 3) / 4, 2), 256>>>(h1, rf1, nei0, h2, rf2, nei1, n);

    // 4 agg tanh sums
    gemv_g<<<dim3(tiles, 4), 128, GEMV_SMEM>>>(aggW0, aggb0, aggW1, aggb1, n);

    beta_rel_kernel<<<1, 64>>>(aggatt0, aggatt1, n);

    combine_g<<<dim3(tiles, 2), 128, GEMV_SMEM>>>(interW, interb, n);

    beta_inter_kernel<<<1, 32>>>(interatt, n);

    final_kernel<<<(n * 32 + 255) / 256, 256>>>(tf, out, n);
}

// round 14
// speedup vs baseline: 1.0430x; 1.0430x over previous
#include <cuda_runtime.h>

#define NMAX 100000
#define M1MAX 200000
#define M2MAX 100000

// ---------------- scratch (device globals; no allocations) ----------------
__device__ float g_cref[4][NMAX];           // per-branch c_ref = refp . att[:64]
__device__ float g_l1[4][NMAX];             // per-branch L1(refp)
__device__ float g_E[4][(size_t)NMAX * 64]; // e_attr0, e_rel0, e_attr1, e_rel1
__device__ float g_E0[(size_t)NMAX * 64];   // elu-combined relation-0 embedding
__device__ float g_E1[(size_t)NMAX * 64];   // elu-combined relation-1 embedding
__device__ float g_acc[7 * 64];             // tanh-GEMV column sums
__device__ float g_beta[8];                 // 0-3 intra betas, 4-6 inter betas
__device__ float2 g_cd_t1[M1MAX];           // h1:  (row.att2, L1)
__device__ float2 g_cd_r1[M1MAX];           // rf1
__device__ float2 g_cd_t2[M2MAX];           // h2
__device__ float2 g_cd_r2[M2MAX];           // rf2

// ---------------- helpers ----------------
static __device__ __forceinline__ float2 ffma2(float2 a, float2 b, float2 c) {
    float2 d;
    asm("fma.rn.f32x2 %0, %1, %2, %3;"
        : "=l"(reinterpret_cast<unsigned long long &>(d))
        : "l"(reinterpret_cast<unsigned long long &>(a)),
          "l"(reinterpret_cast<unsigned long long &>(b)),
          "l"(reinterpret_cast<unsigned long long &>(c)));
    return d;
}

static __device__ __forceinline__ float2 wred2(float2 v) {
#pragma unroll
    for (int m = 16; m > 0; m >>= 1) {
        v.x += __shfl_xor_sync(0xffffffffu, v.x, m);
        v.y += __shfl_xor_sync(0xffffffffu, v.y, m);
    }
    return v;
}

static __device__ __forceinline__ float wredf(float v) {
#pragma unroll
    for (int m = 16; m > 0; m >>= 1) v += __shfl_xor_sync(0xffffffffu, v, m);
    return v;
}

static __device__ __forceinline__ float eluf(float x) { return x > 0.f ? x : expm1f(x); }

static __device__ __forceinline__ float tanha(float x) {
    float y;
    asm("tanh.approx.f32 %0, %1;" : "=f"(y) : "f"(x));
    return y;
}

extern __shared__ float smdyn[];

// GEMM-tile constants: M=128 nodes, N=64 outputs, K=64. 128 thr = 16(m) x 8(n).
// Thread (im,in) owns m = 8*im..8*im+7 and j in {4*in..4*in+3, 32+4*in..32+4*in+3}.
#define XS_F 8192   // xs[64][128]  transposed x
#define WS_F 4096   // ws[64][64]   transposed W (ws[k][j] = W[j][k])

// stage W transposed into ws: thread t: j=t&63, k-half=t>>6
static __device__ __forceinline__ void stage_w(float *ws, const float *__restrict__ W,
                                               int tid) {
    int j = tid & 63, half = tid >> 6;
    const float4 *wg = (const float4 *)(W + j * 64 + half * 32);
#pragma unroll
    for (int i = 0; i < 8; i++) {
        float4 w4 = __ldg(wg + i);
        int k = half * 32 + 4 * i;
        ws[k * 64 + j] = w4.x;
        ws[(k + 1) * 64 + j] = w4.y;
        ws[(k + 2) * 64 + j] = w4.z;
        ws[(k + 3) * 64 + j] = w4.w;
    }
}

// stage one x row (row rr of x) into transposed xs column tid
static __device__ __forceinline__ void stage_x(float *xs, const float *__restrict__ x,
                                               int rr, int tid) {
    const float4 *xg = (const float4 *)(x + (size_t)rr * 64);
#pragma unroll
    for (int i = 0; i < 16; i++) {
        float4 v = __ldg(xg + i);
        int k = 4 * i;
        xs[k * 128 + tid] = v.x;
        xs[(k + 1) * 128 + tid] = v.y;
        xs[(k + 2) * 128 + tid] = v.z;
        xs[(k + 3) * 128 + tid] = v.w;
    }
}

// K-loop with UNCONDITIONAL register double-buffered prefetch. The k+1 loads
// are issued first in every body with no guard; at k=63 they read one
// iteration past xs/ws into the adjacent par/red smem regions (allocated,
// values never used). Load->use distance = one full body >= LDS latency.
#define FMA_M(CX)                                                        \
    do {                                                                 \
        float2 xd = make_float2(CX, CX);                                 \
        acc[MM][0] = ffma2(xd, q0, acc[MM][0]);                          \
        acc[MM][1] = ffma2(xd, q1, acc[MM][1]);                          \
        acc[MM][2] = ffma2(xd, q2, acc[MM][2]);                          \
        acc[MM][3] = ffma2(xd, q3, acc[MM][3]);                          \
    } while (0)

static __device__ __forceinline__ void mm_loop(const float *xs, const float *ws,
                                               float2 acc[8][4], int im, int in) {
    const float4 *xp = (const float4 *)&xs[8 * im];        // +32 float4 per k
    const float4 *wap = (const float4 *)&ws[4 * in];       // +16 float4 per k
    const float4 *wbp = (const float4 *)&ws[32 + 4 * in];
    float4 px0 = xp[0], px1 = xp[1], pwa = wap[0], pwb = wbp[0];
#pragma unroll 4
    for (int k = 0; k < 64; k++) {
        float4 cx0 = px0, cx1 = px1, cwa = pwa, cwb = pwb;
        // unconditional prefetch of iteration k+1
        px0 = xp[32 * (k + 1)];
        px1 = xp[32 * (k + 1) + 1];
        pwa = wap[16 * (k + 1)];
        pwb = wbp[16 * (k + 1)];
        float2 q0 = make_float2(cwa.x, cwa.y), q1 = make_float2(cwa.z, cwa.w);
        float2 q2 = make_float2(cwb.x, cwb.y), q3 = make_float2(cwb.z, cwb.w);
        {
#define MM 0
            FMA_M(cx0.x);
#undef MM
#define MM 1
            FMA_M(cx0.y);
#undef MM
#define MM 2
            FMA_M(cx0.z);
#undef MM
#define MM 3
            FMA_M(cx0.w);
#undef MM
#define MM 4
            FMA_M(cx1.x);
#undef MM
#define MM 5
            FMA_M(cx1.y);
#undef MM
#define MM 6
            FMA_M(cx1.z);
#undef MM
#define MM 7
            FMA_M(cx1.w);
#undef MM
        }
    }
}

// ---------------- kernels ----------------
__global__ void init_kernel() {
    int t = threadIdx.x;
    if (t < 7 * 64) g_acc[t] = 0.f;
}

// Per-table-row precompute: out[row] = (row . att2, L1(row)) for two tables.
__global__ void __launch_bounds__(256) precomp_kernel(
    const float *__restrict__ tab, const float *__restrict__ rtab,
    float2 *__restrict__ outT, float2 *__restrict__ outR,
    const float *__restrict__ attT2, const float *__restrict__ attR2, int m) {
    int w = threadIdx.x >> 5, l = threadIdx.x & 31;
    float2 aT = __ldg((const float2 *)attT2 + l);
    float2 aR = __ldg((const float2 *)attR2 + l);
    int row = blockIdx.x * 8 + w;
    if (row >= m) return;
    float2 v = __ldg((const float2 *)(tab + (size_t)row * 64) + l);
    float2 q = wred2(make_float2(v.x * aT.x + v.y * aT.y, fabsf(v.x) + fabsf(v.y)));
    float2 u = __ldg((const float2 *)(rtab + (size_t)row * 64) + l);
    float2 p = wred2(make_float2(u.x * aR.x + u.y * aR.y, fabsf(u.x) + fabsf(u.y)));
    if (l == 0) { outT[row] = q; outR[row] = p; }
}

// Block-GEMM prep + tf-gemv:
// y=0:(h0,Wr0,att0)->s0  y=1:(h0,Wr1,att1)->s2
// y=2:(rf0,Wr2_0,att2_0)->s1  y=3:(rf0,Wr2_1,att2_1)->s3
// y=4: tanh column sums of tf @ interW^T + interb -> g_acc slot 6
// dyn smem floats: xs 8192 | ws 4096 | par 128 | red 1024
__global__ void __launch_bounds__(128, 4) prep_g(
    const float *__restrict__ h0, const float *__restrict__ rf0,
    const float *__restrict__ tf,
    const float *__restrict__ W0, const float *__restrict__ b0, const float *__restrict__ a0,
    const float *__restrict__ W1, const float *__restrict__ b1, const float *__restrict__ a1,
    const float *__restrict__ W2, const float *__restrict__ b2, const float *__restrict__ a2,
    const float *__restrict__ W3, const float *__restrict__ b3, const float *__restrict__ a3,
    const float *__restrict__ interW, const float *__restrict__ interb,
    int n) {
    float *xs = smdyn, *ws = smdyn + XS_F, *par = ws + WS_F, *red = par + 128;
    int y = blockIdx.y;
    const float *x, *W, *b, *att;
    int slot;
    if (y == 0)      { x = h0;  W = W0; b = b0; att = a0; slot = 0; }
    else if (y == 1) { x = h0;  W = W1; b = b1; att = a1; slot = 2; }
    else if (y == 2) { x = rf0; W = W2; b = b2; att = a2; slot = 1; }
    else if (y == 3) { x = rf0; W = W3; b = b3; att = a3; slot = 3; }
    else             { x = tf;  W = interW; b = interb; att = interb; slot = 6; }
    int tid = threadIdx.x;
    stage_w(ws, W, tid);
    if (tid < 64) { par[tid] = b[tid]; par[64 + tid] = att[tid]; }
    int base = blockIdx.x * 128;
    int r = base + tid;
    bool act = (r < n);
    stage_x(xs, x, act ? r : (n - 1), tid);
    __syncthreads();
    int im = tid >> 3, in = tid & 7;
    float2 acc[8][4];
#pragma unroll
    for (int m = 0; m < 8; m++)
#pragma unroll
        for (int p = 0; p < 4; p++) acc[m][p] = make_float2(0.f, 0.f);
    mm_loop(xs, ws, acc, im, in);
    int jb[4] = {4 * in, 4 * in + 2, 32 + 4 * in, 32 + 4 * in + 2};
    if (y < 4) {
        float crv[8], l1v[8];
#pragma unroll
        for (int m = 0; m < 8; m++) {
            float cr = 0.f, l1 = 0.f;
#pragma unroll
            for (int p = 0; p < 4; p++) {
                int j = jb[p];
                float r0 = acc[m][p].x + par[j];
                float r1 = acc[m][p].y + par[j + 1];
                cr = fmaf(r0, par[64 + j], cr);
                cr = fmaf(r1, par[64 + j + 1], cr);
                l1 += fabsf(r0) + fabsf(r1);
            }
            crv[m] = cr; l1v[m] = l1;
        }
        __syncthreads();
#pragma unroll
        for (int m = 0; m < 8; m++) red[in * 128 + 8 * im + m] = crv[m];
        __syncthreads();
        float crt = 0.f;
#pragma unroll
        for (int q = 0; q < 8; q++) crt += red[q * 128 + tid];
        __syncthreads();
#pragma unroll
        for (int m = 0; m < 8; m++) red[in * 128 + 8 * im + m] = l1v[m];
        __syncthreads();
        float l1t = 0.f;
#pragma unroll
        for (int q = 0; q < 8; q++) l1t += red[q * 128 + tid];
        if (act) { g_cref[slot][r] = crt; g_l1[slot][r] = l1t; }
    } else {
        float s[8];
#pragma unroll
        for (int jj = 0; jj < 8; jj++) s[jj] = 0.f;
#pragma unroll
        for (int m = 0; m < 8; m++) {
            bool am = (base + 8 * im + m) < n;
#pragma unroll
            for (int p = 0; p < 4; p++) {
                int j = jb[p];
                if (am) {
                    s[2 * p] += tanha(acc[m][p].x + par[j]);
                    s[2 * p + 1] += tanha(acc[m][p].y + par[j + 1]);
                }
            }
        }
        __syncthreads();
#pragma unroll
        for (int p = 0; p < 4; p++) {
            red[im * 64 + jb[p]] = s[2 * p];
            red[im * 64 + jb[p] + 1] = s[2 * p + 1];
        }
        __syncthreads();
        if (tid < 64) {
            float tot = 0.f;
#pragma unroll
            for (int q = 0; q < 16; q++) tot += red[q * 64 + tid];
            atomicAdd(&g_acc[slot * 64 + tid], tot);
        }
    }
}

// Block-GEMM tanh column sums for the 4 E branches (y=0..3).
__global__ void __launch_bounds__(128, 4) gemv_g(
    const float *__restrict__ aggW0, const float *__restrict__ aggb0,
    const float *__restrict__ aggW1, const float *__restrict__ aggb1, int n) {
    float *xs = smdyn, *ws = smdyn + XS_F, *bs = ws + WS_F, *red = bs + 64;
    int y = blockIdx.y;
    const float *x = g_E[y];
    const float *W = (y < 2) ? aggW0 : aggW1;
    const float *b = (y < 2) ? aggb0 : aggb1;
    int slot = y;
    int tid = threadIdx.x;
    stage_w(ws, W, tid);
    if (tid < 64) bs[tid] = b[tid];
    int base = blockIdx.x * 128;
    int r = base + tid;
    stage_x(xs, x, (r < n) ? r : (n - 1), tid);
    __syncthreads();
    int im = tid >> 3, in = tid & 7;
    float2 acc[8][4];
#pragma unroll
    for (int m = 0; m < 8; m++)
#pragma unroll
        for (int p = 0; p < 4; p++) acc[m][p] = make_float2(0.f, 0.f);
    mm_loop(xs, ws, acc, im, in);
    int jb[4] = {4 * in, 4 * in + 2, 32 + 4 * in, 32 + 4 * in + 2};
    float s[8];
#pragma unroll
    for (int jj = 0; jj < 8; jj++) s[jj] = 0.f;
#pragma unroll
    for (int m = 0; m < 8; m++) {
        bool am = (base + 8 * im + m) < n;
#pragma unroll
        for (int p = 0; p < 4; p++) {
            int j = jb[p];
            if (am) {
                s[2 * p] += tanha(acc[m][p].x + bs[j]);
                s[2 * p + 1] += tanha(acc[m][p].y + bs[j + 1]);
            }
        }
    }
    __syncthreads();
#pragma unroll
    for (int p = 0; p < 4; p++) {
        red[im * 64 + jb[p]] = s[2 * p];
        red[im * 64 + jb[p] + 1] = s[2 * p + 1];
    }
    __syncthreads();
    if (tid < 64) {
        float tot = 0.f;
#pragma unroll
        for (int q = 0; q < 16; q++) tot += red[q * 64 + tid];
        atomicAdd(&g_acc[slot * 64 + tid], tot);
    }
}

// fused: c = elu(ba*eA + bb*eB); store c; tanh column sums of c@interW^T+b.
__global__ void __launch_bounds__(128, 4) combine_g(
    const float *__restrict__ interW, const float *__restrict__ interb, int n) {
    float *xs = smdyn, *ws = smdyn + XS_F, *bs = ws + WS_F, *red = bs + 64;
    int y = blockIdx.y;
    const float *eA = g_E[2 * y], *eB = g_E[2 * y + 1];
    float *outb = y ? g_E1 : g_E0;
    float ba = g_beta[2 * y], bb = g_beta[2 * y + 1];
    int tid = threadIdx.x;
    stage_w(ws, interW, tid);
    if (tid < 64) bs[tid] = interb[tid];
    int base = blockIdx.x * 128;
    int r = base + tid;
    bool act = (r < n);
    int rr = act ? r : (n - 1);
    {
        const float4 *ag = (const float4 *)(eA + (size_t)rr * 64);
        const float4 *bg = (const float4 *)(eB + (size_t)rr * 64);
        float4 *og = (float4 *)(outb + (size_t)rr * 64);
#pragma unroll
        for (int i = 0; i < 16; i++) {
            float4 a = __ldg(ag + i), v = __ldg(bg + i);
            float4 c;
            c.x = eluf(ba * a.x + bb * v.x);
            c.y = eluf(ba * a.y + bb * v.y);
            c.z = eluf(ba * a.z + bb * v.z);
            c.w = eluf(ba * a.w + bb * v.w);
            if (act) og[i] = c;
            int k = 4 * i;
            xs[k * 128 + tid] = c.x;
            xs[(k + 1) * 128 + tid] = c.y;
            xs[(k + 2) * 128 + tid] = c.z;
            xs[(k + 3) * 128 + tid] = c.w;
        }
    }
    __syncthreads();
    int im = tid >> 3, in = tid & 7;
    float2 acc[8][4];
#pragma unroll
    for (int m = 0; m < 8; m++)
#pragma unroll
        for (int p = 0; p < 4; p++) acc[m][p] = make_float2(0.f, 0.f);
    mm_loop(xs, ws, acc, im, in);
    int jb[4] = {4 * in, 4 * in + 2, 32 + 4 * in, 32 + 4 * in + 2};
    float s[8];
#pragma unroll
    for (int jj = 0; jj < 8; jj++) s[jj] = 0.f;
#pragma unroll
    for (int m = 0; m < 8; m++) {
        bool am = (base + 8 * im + m) < n;
#pragma unroll
        for (int p = 0; p < 4; p++) {
            int j = jb[p];
            if (am) {
                s[2 * p] += tanha(acc[m][p].x + bs[j]);
                s[2 * p + 1] += tanha(acc[m][p].y + bs[j + 1]);
            }
        }
    }
    __syncthreads();
#pragma unroll
    for (int p = 0; p < 4; p++) {
        red[im * 64 + jb[p]] = s[2 * p];
        red[im * 64 + jb[p] + 1] = s[2 * p + 1];
    }
    __syncthreads();
    if (tid < 64) {
        float tot = 0.f;
#pragma unroll
        for (int q = 0; q < 16; q++) tot += red[q * 64 + tid];
        atomicAdd(&g_acc[(4 + y) * 64 + tid], tot);
    }
}

static __device__ __forceinline__ void do_branch_v2(
    const float *__restrict__ tab, const float2 *__restrict__ cdl1,
    const int *idx, float cref, float l1ref, float *__restrict__ eout, int l) {
    float2 v[8];
    float sc[8];
#pragma unroll
    for (int s = 0; s < 8; s++)
        v[s] = __ldg((const float2 *)(tab + (size_t)idx[s] * 64) + l);
#pragma unroll
    for (int s = 0; s < 8; s++) {
        float2 cd = __ldg(cdl1 + idx[s]);
        float t = __fdividef(cref + cd.x, fmaxf(l1ref + cd.y, 1e-12f));
        sc[s] = t > 0.f ? t : 0.01f * t;  // leaky_relu 0.01
    }
    float mx = sc[0];
#pragma unroll
    for (int s = 1; s < 8; s++) mx = fmaxf(mx, sc[s]);
    float sum = 0.f;
#pragma unroll
    for (int s = 0; s < 8; s++) { sc[s] = __expf(sc[s] - mx); sum += sc[s]; }
    float inv = __fdividef(1.f, sum);
    float2 o = make_float2(0.f, 0.f);
#pragma unroll
    for (int s = 0; s < 8; s++) {
        float ww = sc[s] * inv;
        o.x = fmaf(ww, v[s].x, o.x);
        o.y = fmaf(ww, v[s].y, o.y);
    }
    *((float2 *)eout + l) = o;
}

// warp-per-(node, branch) attention: 8 warps = 4 nodes x 2 branches per block.
__global__ void __launch_bounds__(256) attn_y(
    const float *__restrict__ t1, const float *__restrict__ r1, const int *__restrict__ n0,
    const float *__restrict__ t2, const float *__restrict__ r2, const int *__restrict__ n1,
    int n) {
    int y = blockIdx.y;
    const float *tab = y ? t2 : t1;
    const float *rtab = y ? r2 : r1;
    const int *nei = y ? n1 : n0;
    const float2 *cdA = y ? g_cd_t2 : g_cd_t1;
    const float2 *cdR = y ? g_cd_r2 : g_cd_r1;
    int cidx = y * 2;
    int tid = threadIdx.x, w = tid >> 5, l = tid & 31;
    int node = blockIdx.x * 4 + (w >> 1);
    int br = w & 1;
    if (node >= n) return;
    const float *t = br ? rtab : tab;
    const float2 *cd = br ? cdR : cdA;
    int slot = cidx + br;
    const int4 *np = (const int4 *)(nei + (size_t)node * 8);
    int4 i0 = __ldg(np), i1 = __ldg(np + 1);
    int idx[8] = {i0.x, i0.y, i0.z, i0.w, i1.x, i1.y, i1.z, i1.w};
    do_branch_v2(t, cd, idx, g_cref[slot][node], g_l1[slot][node],
                 &g_E[slot][(size_t)node * 64], l);
}

__global__ void beta_rel_kernel(const float *__restrict__ agg0,
                                const float *__restrict__ agg1, int n) {
    int tid = threadIdx.x;
    int r = tid >> 5, l = tid & 31;
    if (r > 1) return;
    const float *aat = r ? agg1 : agg0;
    float invN = 1.f / (float)n;
    float2 at = __ldg((const float2 *)aat + l);
    const float *accA = g_acc + (2 * r) * 64;
    const float *accB = g_acc + (2 * r + 1) * 64;
    float pa = (accA[2 * l] * invN) * at.x + (accA[2 * l + 1] * invN) * at.y;
    float pb = (accB[2 * l] * invN) * at.x + (accB[2 * l + 1] * invN) * at.y;
    float2 q = wred2(make_float2(pa, pb));
    if (l == 0) {
        float m = fmaxf(q.x, q.y);
        float ea = expf(q.x - m), eb = expf(q.y - m);
        float inv = 1.f / (ea + eb);
        g_beta[2 * r] = ea * inv;
        g_beta[2 * r + 1] = eb * inv;
    }
}

__global__ void beta_inter_kernel(const float *__restrict__ interatt, int n) {
    int l = threadIdx.x;
    float invN = 1.f / (float)n;
    float2 at = __ldg((const float2 *)interatt + l);
    float p[3];
#pragma unroll
    for (int k = 0; k < 3; k++) {
        float px = (g_acc[(4 + k) * 64 + 2 * l] * invN) * at.x +
                   (g_acc[(4 + k) * 64 + 2 * l + 1] * invN) * at.y;
        p[k] = wredf(px);
    }
    if (l == 0) {
        float m = fmaxf(p[0], fmaxf(p[1], p[2]));
        float e0 = expf(p[0] - m), e1 = expf(p[1] - m), e2 = expf(p[2] - m);
        float inv = 1.f / (e0 + e1 + e2);
        g_beta[4] = e0 * inv;
        g_beta[5] = e1 * inv;
        g_beta[6] = e2 * inv;
    }
}

__global__ void final_kernel(const float *__restrict__ tf, float *__restrict__ out, int n) {
    int i = blockIdx.x * blockDim.x + threadIdx.x;
    if (i >= n * 32) return;
    float b0 = g_beta[4], b1 = g_beta[5], b2 = g_beta[6];
    float2 e0 = ((const float2 *)g_E0)[i];
    float2 e1 = ((const float2 *)g_E1)[i];
    float2 t = ((const float2 *)tf)[i];
    float2 o;
    o.x = b0 * e0.x + b1 * e1.x + b2 * t.x;
    o.y = b0 * e0.y + b1 * e1.y + b2 * t.y;
    ((float2 *)out)[i] = o;
}

// ---------------- launch ----------------
extern "C" void kernel_launch(void *const *d_in, const int *in_sizes, int n_in,
                              void *d_out, int out_size) {
    const float *tf = (const float *)d_in[0];
    const float *h0 = (const float *)d_in[1];
    const float *h1 = (const float *)d_in[2];
    const float *h2 = (const float *)d_in[3];
    const float *rf0 = (const float *)d_in[4];
    const float *rf1 = (const float *)d_in[5];
    const float *rf2 = (const float *)d_in[6];
    const int *nei0 = (const int *)d_in[7];
    const int *nei1 = (const int *)d_in[8];
    const float *att0 = (const float *)d_in[9];
    const float *att2_0 = (const float *)d_in[10];
    const float *Wr0 = (const float *)d_in[11];
    const float *br0 = (const float *)d_in[12];
    const float *Wr2_0 = (const float *)d_in[13];
    const float *br2_0 = (const float *)d_in[14];
    const float *aggW0 = (const float *)d_in[15];
    const float *aggb0 = (const float *)d_in[16];
    const float *aggatt0 = (const float *)d_in[17];
    const float *att1 = (const float *)d_in[18];
    const float *att2_1 = (const float *)d_in[19];
    const float *Wr1 = (const float *)d_in[20];
    const float *br1 = (const float *)d_in[21];
    const float *Wr2_1 = (const float *)d_in[22];
    const float *br2_1 = (const float *)d_in[23];
    const float *aggW1 = (const float *)d_in[24];
    const float *aggb1 = (const float *)d_in[25];
    const float *aggatt1 = (const float *)d_in[26];
    const float *interW = (const float *)d_in[27];
    const float *interb = (const float *)d_in[28];
    const float *interatt = (const float *)d_in[29];

    int n = in_sizes[0] / 64;
    if (n > NMAX) n = NMAX;
    int m1 = in_sizes[2] / 64; if (m1 > M1MAX) m1 = M1MAX;
    int m2 = in_sizes[3] / 64; if (m2 > M2MAX) m2 = M2MAX;
    float *out = (float *)d_out;

    float2 *cd_t1, *cd_r1, *cd_t2, *cd_r2;
    cudaGetSymbolAddress((void **)&cd_t1, g_cd_t1);
    cudaGetSymbolAddress((void **)&cd_r1, g_cd_r1);
    cudaGetSymbolAddress((void **)&cd_t2, g_cd_t2);
    cudaGetSymbolAddress((void **)&cd_r2, g_cd_r2);

    const int PREP_SMEM = (XS_F + WS_F + 128 + 1024) * 4;   // 53760 B
    const int GEMV_SMEM = (XS_F + WS_F + 64 + 1024) * 4;    // 53504 B
    cudaFuncSetAttribute(prep_g, cudaFuncAttributeMaxDynamicSharedMemorySize, PREP_SMEM);
    cudaFuncSetAttribute(gemv_g, cudaFuncAttributeMaxDynamicSharedMemorySize, GEMV_SMEM);
    cudaFuncSetAttribute(combine_g, cudaFuncAttributeMaxDynamicSharedMemorySize, GEMV_SMEM);

    init_kernel<<<1, 512>>>();

    precomp_kernel<<<(m1 + 7) / 8, 256>>>(h1, rf1, cd_t1, cd_r1, att0 + 64, att2_0 + 64, m1);
    precomp_kernel<<<(m2 + 7) / 8, 256>>>(h2, rf2, cd_t2, cd_r2, att1 + 64, att2_1 + 64, m2);

    int tiles = (n + 127) / 128;

    // prep (4 branch slices) + tf inter tanh sums (slice 4), one launch
    prep_g<<<dim3(tiles, 5), 128, PREP_SMEM>>>(h0, rf0, tf,
                                               Wr0, br0, att0,
                                               Wr1, br1, att1,
                                               Wr2_0, br2_0, att2_0,
                                               Wr2_1, br2_1, att2_1,
                                               interW, interb, n);

    // warp-per-(node,branch) attention, both relations
    attn_y<<<dim3((n + 3) / 4, 2), 256>>>(h1, rf1, nei0, h2, rf2, nei1, n);

    // 4 agg tanh sums
    gemv_g<<<dim3(tiles, 4), 128, GEMV_SMEM>>>(aggW0, aggb0, aggW1, aggb1, n);

    beta_rel_kernel<<<1, 64>>>(aggatt0, aggatt1, n);

    combine_g<<<dim3(tiles, 2), 128, GEMV_SMEM>>>(interW, interb, n);

    beta_inter_kernel<<<1, 32>>>(interatt, n);

    final_kernel<<<(n * 32 + 255) / 256, 256>>>(tf, out, n);
}